// round 8
// baseline (speedup 1.0000x reference)
#include <cuda_runtime.h>
#include <mma.h>
#include <cstdint>
#include <cstddef>

using namespace nvcuda;

constexpr int S  = 10;
constexpr int D  = 512;
constexpr int NQ = 4096;
constexpr int NP = 1024;

// ------------------------- scratch (__device__ globals) ---------------------
__device__ float g_W[S * D * D];              // fp32 W [s][d][e]
__device__ float g_b[S * D];
__device__ float g_tq[(size_t)S * NQ * D];
__device__ float g_sqq[S * NQ];
__device__ float g_sqp[NP];
__device__ float g_dists[(size_t)S * NQ * NP];

// ------------------------------ Threefry-2x32 -------------------------------
__host__ __device__ __forceinline__ unsigned rotl32(unsigned x, int d) {
    return (x << d) | (x >> (32 - d));
}
__host__ __device__ __forceinline__ void tf2x32(unsigned k0, unsigned k1,
                                                unsigned &x0, unsigned &x1) {
    unsigned k2 = k0 ^ k1 ^ 0x1BD11BDAu;
    x0 += k0; x1 += k1;
#define TFR(r) { x0 += x1; x1 = rotl32(x1, r) ^ x0; }
    TFR(13) TFR(15) TFR(26) TFR(6)   x0 += k1; x1 += k2 + 1u;
    TFR(17) TFR(29) TFR(16) TFR(24)  x0 += k2; x1 += k0 + 2u;
    TFR(13) TFR(15) TFR(26) TFR(6)   x0 += k0; x1 += k1 + 3u;
    TFR(17) TFR(29) TFR(16) TFR(24)  x0 += k1; x1 += k2 + 4u;
    TFR(13) TFR(15) TFR(26) TFR(6)   x0 += k2; x1 += k0 + 5u;
#undef TFR
}
__device__ __forceinline__ unsigned jax_bits32(unsigned k0, unsigned k1, unsigned i) {
    unsigned x0 = 0u, x1 = i;
    tf2x32(k0, k1, x0, x1);
    return x0 ^ x1;
}
__device__ __forceinline__ float erfinv_xla(float x) {
    float w = -log1pf(-x * x);
    float p;
    if (w < 5.0f) {
        w -= 2.5f;
        p = 2.81022636e-08f;
        p = fmaf(p, w, 3.43273939e-07f);
        p = fmaf(p, w, -3.5233877e-06f);
        p = fmaf(p, w, -4.39150654e-06f);
        p = fmaf(p, w, 0.00021858087f);
        p = fmaf(p, w, -0.00125372503f);
        p = fmaf(p, w, -0.00417768164f);
        p = fmaf(p, w, 0.246640727f);
        p = fmaf(p, w, 1.50140941f);
    } else {
        w = sqrtf(w) - 3.0f;
        p = -0.000200214257f;
        p = fmaf(p, w, 0.000100950558f);
        p = fmaf(p, w, 0.00134934322f);
        p = fmaf(p, w, -0.00367342844f);
        p = fmaf(p, w, 0.00573950773f);
        p = fmaf(p, w, -0.0076224613f);
        p = fmaf(p, w, 0.00943887047f);
        p = fmaf(p, w, 1.00167406f);
        p = fmaf(p, w, 2.83297682f);
    }
    return p * x;
}
__device__ __forceinline__ float bits_to_normal(unsigned bits) {
    float f = __uint_as_float((bits >> 9) | 0x3F800000u) - 1.0f;
    float u = fmaxf(-0.99999994f, f * 2.0f - 0.99999994f);
    return 1.41421356237f * erfinv_xla(u);
}

// ------------------------------ prep kernels --------------------------------
__global__ void gen_w_kernel(const float* __restrict__ wmu,
                             const float* __restrict__ wrho,
                             unsigned k0, unsigned k1) {
    int i = blockIdx.x * blockDim.x + threadIdx.x;
    if (i >= S * D * D) return;
    float eps = bits_to_normal(jax_bits32(k0, k1, (unsigned)i));
    int j = i & (D * D - 1);
    g_W[i] = fmaf(log1pf(expf(wrho[j])), eps, wmu[j]);
}

__global__ void gen_b_kernel(const float* __restrict__ bmu,
                             const float* __restrict__ brho,
                             unsigned k0, unsigned k1) {
    int i = blockIdx.x * blockDim.x + threadIdx.x;
    if (i >= S * D) return;
    float eps = bits_to_normal(jax_bits32(k0, k1, (unsigned)i));
    int j = i & (D - 1);
    g_b[i] = fmaf(log1pf(expf(brho[j])), eps, bmu[j]);
}

__global__ void sqp_kernel(const float* __restrict__ P) {
    int p = blockIdx.x * 8 + (threadIdx.x >> 5);
    int lane = threadIdx.x & 31;
    const float* row = P + (size_t)p * D;
    float s = 0.f;
    for (int e = lane; e < D; e += 32) { float v = row[e]; s = fmaf(v, v, s); }
    #pragma unroll
    for (int o = 16; o; o >>= 1) s += __shfl_xor_sync(0xffffffffu, s, o);
    if (lane == 0) g_sqp[p] = s;
}

__global__ void sqq_kernel() {
    int row = blockIdx.x * 8 + (threadIdx.x >> 5);
    int lane = threadIdx.x & 31;
    const float* r = g_tq + (size_t)row * D;
    float s = 0.f;
    for (int e = lane; e < D; e += 32) { float v = r[e]; s = fmaf(v, v, s); }
    #pragma unroll
    for (int o = 16; o; o >>= 1) s += __shfl_xor_sync(0xffffffffu, s, o);
    if (lane == 0) g_sqq[row] = s;
}

// ------------------------- GEMM1: fp32 SIMT (proven) ------------------------
__global__ __launch_bounds__(256) void gemm_f32_tq(const float* __restrict__ X) {
    constexpr int N = D, K = D;
    const int s = blockIdx.z;
    const float* __restrict__ A = X;
    const float* __restrict__ B = g_W + (size_t)s * D * D;
    float* __restrict__ C = g_tq + (size_t)s * NQ * D;

    __shared__ float As[16][132];
    __shared__ float Bs[16][128];

    const int tid = threadIdx.x;
    const int tx = tid & 15, ty = tid >> 4;
    const int m0 = blockIdx.y * 128;
    const int n0 = blockIdx.x * 128;

    float acc[8][8];
    #pragma unroll
    for (int i = 0; i < 8; i++)
        #pragma unroll
        for (int j = 0; j < 8; j++) acc[i][j] = 0.f;

    const int ra = tid >> 2, ca = (tid & 3) * 4;
    const int rb = tid >> 5, cb = (tid & 31) * 4;

    for (int k0 = 0; k0 < K; k0 += 16) {
        float4 a0 = *(const float4*)&A[(size_t)(m0 + ra) * K + k0 + ca];
        float4 a1 = *(const float4*)&A[(size_t)(m0 + ra + 64) * K + k0 + ca];
        As[ca + 0][ra] = a0.x; As[ca + 1][ra] = a0.y;
        As[ca + 2][ra] = a0.z; As[ca + 3][ra] = a0.w;
        As[ca + 0][ra + 64] = a1.x; As[ca + 1][ra + 64] = a1.y;
        As[ca + 2][ra + 64] = a1.z; As[ca + 3][ra + 64] = a1.w;
        *(float4*)&Bs[rb][cb]     = *(const float4*)&B[(size_t)(k0 + rb) * N + n0 + cb];
        *(float4*)&Bs[rb + 8][cb] = *(const float4*)&B[(size_t)(k0 + rb + 8) * N + n0 + cb];
        __syncthreads();

        #pragma unroll
        for (int k = 0; k < 16; k++) {
            float a[8], b[8];
            *(float4*)(a)     = *(const float4*)&As[k][ty * 8];
            *(float4*)(a + 4) = *(const float4*)&As[k][ty * 8 + 4];
            *(float4*)(b)     = *(const float4*)&Bs[k][tx * 8];
            *(float4*)(b + 4) = *(const float4*)&Bs[k][tx * 8 + 4];
            #pragma unroll
            for (int i = 0; i < 8; i++)
                #pragma unroll
                for (int j = 0; j < 8; j++)
                    acc[i][j] = fmaf(a[i], b[j], acc[i][j]);
        }
        __syncthreads();
    }

    const float* __restrict__ bias = g_b + (size_t)s * D;
    #pragma unroll
    for (int i = 0; i < 8; i++) {
        int m = m0 + ty * 8 + i;
        #pragma unroll
        for (int j = 0; j < 8; j += 4) {
            int n = n0 + tx * 8 + j;
            float4 v;
            v.x = acc[i][j + 0] + bias[n + 0];
            v.y = acc[i][j + 1] + bias[n + 1];
            v.z = acc[i][j + 2] + bias[n + 2];
            v.w = acc[i][j + 3] + bias[n + 3];
            *(float4*)&C[(size_t)m * N + n] = v;
        }
    }
}

// -------------- GEMM2: wmma tf32x2 distance kernel (no splits) --------------
// Reads fp32 g_tq and fp32 prototypes directly; hi/lo tf32 decomposition done
// inside fragments. 128x128 tile, BK=32, 256 threads (8 warps, 64x32 each).
__global__ __launch_bounds__(256, 2) void gemm_tf32_dist(const float* __restrict__ P) {
    constexpr int BK  = 32;
    constexpr int NCH = D / BK;        // 16
    constexpr int LDT = 40;            // float row stride (32 data + 8 pad)
    constexpr int TILE = 128 * LDT;    // floats per array

    extern __shared__ float fsm[];
    float* sA  = fsm;
    float* sB  = fsm + TILE;
    float* aux = fsm + 2 * TILE;       // 128 floats

    const int s  = blockIdx.z;
    const int m0 = blockIdx.y * 128;
    const int n0 = blockIdx.x * 128;

    const int tid = threadIdx.x;
    const int wid = tid >> 5, lane = tid & 31;
    const int wm  = wid & 1, wn = wid >> 1;    // warp tile rows wm*64, cols wn*32

    const float* __restrict__ A = g_tq + (size_t)s * NQ * D;

    if (tid < 128) aux[tid] = g_sqp[n0 + tid];

    wmma::fragment<wmma::accumulator, 16, 16, 8, float> acc[4][2];
    #pragma unroll
    for (int mt = 0; mt < 4; mt++)
        #pragma unroll
        for (int nt = 0; nt < 2; nt++)
            wmma::fill_fragment(acc[mt][nt], 0.0f);

    for (int c = 0; c < NCH; c++) {
        __syncthreads();
        #pragma unroll
        for (int it = 0; it < 4; it++) {
            int idx = it * 256 + tid;          // [0,1024): 128 rows x 8 float4
            int row = idx >> 3, j = idx & 7;
            size_t ao = (size_t)(m0 + row) * D + c * BK + j * 4;
            size_t bo = (size_t)(n0 + row) * D + c * BK + j * 4;
            *(float4*)&sA[row * LDT + j * 4] = *(const float4*)(A + ao);
            *(float4*)&sB[row * LDT + j * 4] = *(const float4*)(P + bo);
        }
        __syncthreads();

        #pragma unroll
        for (int kk = 0; kk < 4; kk++) {       // 4 k-steps of 8
            wmma::fragment<wmma::matrix_a, 16, 16, 8, wmma::precision::tf32, wmma::row_major> ah[4], al[4];
            wmma::fragment<wmma::matrix_b, 16, 16, 8, wmma::precision::tf32, wmma::col_major> bh[2], bl[2];
            #pragma unroll
            for (int mt = 0; mt < 4; mt++) {
                wmma::load_matrix_sync(ah[mt], sA + (wm * 64 + mt * 16) * LDT + kk * 8, LDT);
                #pragma unroll
                for (int e = 0; e < ah[mt].num_elements; e++) {
                    float v = ah[mt].x[e];
                    float h = wmma::__float_to_tf32(v);
                    ah[mt].x[e] = h;
                    al[mt].x[e] = wmma::__float_to_tf32(v - h);
                }
            }
            #pragma unroll
            for (int nt = 0; nt < 2; nt++) {
                // B col-major: element (k,n) at ptr[n*ldm+k]; sB row n holds k -> OK
                wmma::load_matrix_sync(bh[nt], sB + (wn * 32 + nt * 16) * LDT + kk * 8, LDT);
                #pragma unroll
                for (int e = 0; e < bh[nt].num_elements; e++) {
                    float v = bh[nt].x[e];
                    float h = wmma::__float_to_tf32(v);
                    bh[nt].x[e] = h;
                    bl[nt].x[e] = wmma::__float_to_tf32(v - h);
                }
            }
            #pragma unroll
            for (int mt = 0; mt < 4; mt++)
                #pragma unroll
                for (int nt = 0; nt < 2; nt++) {
                    wmma::mma_sync(acc[mt][nt], ah[mt], bh[nt], acc[mt][nt]);
                    wmma::mma_sync(acc[mt][nt], ah[mt], bl[nt], acc[mt][nt]);
                    wmma::mma_sync(acc[mt][nt], al[mt], bh[nt], acc[mt][nt]);
                }
        }
    }

    // --------------------------- epilogue ------------------------------------
    __syncthreads();                           // staging dead; reuse as scratch
    float* scratch = fsm + wid * 512;          // per-warp 16x32 fp32
    #pragma unroll
    for (int mt = 0; mt < 4; mt++) {
        wmma::store_matrix_sync(scratch,      acc[mt][0], 32, wmma::mem_row_major);
        wmma::store_matrix_sync(scratch + 16, acc[mt][1], 32, wmma::mem_row_major);
        __syncwarp();
        #pragma unroll
        for (int r = 0; r < 16; r++) {
            int row = m0 + wm * 64 + mt * 16 + r;
            float q2 = g_sqq[s * NQ + row];
            float cr = scratch[r * 32 + lane];
            float p2 = aux[wn * 32 + lane];
            float dv = sqrtf(fmaxf(q2 + p2 - 2.0f * cr, 1e-12f));
            g_dists[(size_t)(s * NQ + row) * NP + n0 + wn * 32 + lane] = dv;
        }
        __syncwarp();
    }
}

// ------------------------------ reduction -----------------------------------
__global__ void reduce_kernel(float* __restrict__ out) {
    size_t i = (size_t)blockIdx.x * blockDim.x + threadIdx.x;
    float v[S];
    float sum = 0.f;
    #pragma unroll
    for (int s = 0; s < S; s++) {
        v[s] = g_dists[(size_t)s * NQ * NP + i];
        sum += v[s];
    }
    float mean = sum * (1.0f / S);
    float m2 = 0.f;
    #pragma unroll
    for (int s = 0; s < S; s++) {
        float d = v[s] - mean;
        m2 = fmaf(d, d, m2);
    }
    out[i] = mean;
    out[(size_t)NQ * NP + i] = sqrtf(m2 * (1.0f / (S - 1)));
}

// ------------------------------ launcher ------------------------------------
extern "C" void kernel_launch(void* const* d_in, const int* in_sizes, int n_in,
                              void* d_out, int out_size) {
    const float* X    = (const float*)d_in[0];
    const float* P    = (const float*)d_in[1];
    const float* wmu  = (const float*)d_in[2];
    const float* wrho = (const float*)d_in[3];
    const float* bmu  = (const float*)d_in[4];
    const float* brho = (const float*)d_in[5];
    float* out = (float*)d_out;

    constexpr int SMEM_TOTAL = (2 * 128 * 40 + 128) * 4;   // 41472 B
    cudaFuncSetAttribute(gemm_tf32_dist, cudaFuncAttributeMaxDynamicSharedMemorySize, SMEM_TOTAL);

    const unsigned key0 = 0u, key1 = 42u;
    unsigned kw0, kw1, kb0, kb1;
    { unsigned x0 = 0u, x1 = 0u; tf2x32(key0, key1, x0, x1); kw0 = x0; kw1 = x1; }
    { unsigned x0 = 0u, x1 = 1u; tf2x32(key0, key1, x0, x1); kb0 = x0; kb1 = x1; }

    gen_w_kernel<<<(S * D * D) / 256, 256>>>(wmu, wrho, kw0, kw1);
    gen_b_kernel<<<(S * D) / 256, 256>>>(bmu, brho, kb0, kb1);
    sqp_kernel<<<NP / 8, 256>>>(P);

    gemm_f32_tq<<<dim3(D / 128, NQ / 128, S), 256>>>(X);
    sqq_kernel<<<(S * NQ) / 8, 256>>>();

    gemm_tf32_dist<<<dim3(NP / 128, NQ / 128, S), 256, SMEM_TOTAL>>>(P);

    reduce_kernel<<<(NQ * NP) / 256, 256>>>(out);
}